// round 14
// baseline (speedup 1.0000x reference)
#include <cuda_runtime.h>
#include <cuda_bf16.h>
#include <math.h>
#include <stdint.h>

#define NNODES 50000
#define NEDGES 800000
#define HID    128
#define NLAYERS 3
#define NGRAPHS 256
#define BN_EPS 1e-5f

// ---------------- scratch ----------------
__device__ float g_h[NNODES * HID];
__device__ float g_t[NNODES * HID];
__device__ float g_s[NNODES * HID];
__device__ float g_gi[NNODES * 3 * HID];
__device__ float g_gh[NNODES * 3 * HID];
__device__ float g_deg[NNODES];
__device__ int   g_offs[NGRAPHS + 1];
__device__ float g_z[NGRAPHS * 2 * HID];
__device__ float g_bc[NLAYERS * 384];
// bf16 hi/lo activation mirrors
__device__ __nv_bfloat16 g_xb[NNODES * HID], g_xl[NNODES * HID];
__device__ __nv_bfloat16 g_hb[NNODES * HID], g_hl[NNODES * HID];
__device__ __nv_bfloat16 g_sb[NNODES * HID], g_sl[NNODES * HID];
// bf16 hi/lo weights [n][k=128]:
// rows 0..127: lin ; layer l: 128+l*512 = [w1h(128); whh(384)] ; wc: 1664+l*384
#define WROWS 2816
__device__ __nv_bfloat16 g_wh[WROWS * 128];
__device__ __nv_bfloat16 g_wl[WROWS * 128];

__device__ __forceinline__ uint32_t smem_u32(const void* p) {
    uint32_t a;
    asm("{ .reg .u64 t; cvta.to.shared.u64 t, %1; cvt.u32.u64 %0, t; }"
        : "=r"(a) : "l"(p));
    return a;
}
__device__ __forceinline__ uint32_t pkbf(__nv_bfloat16 a, __nv_bfloat16 b) {
    __nv_bfloat162 t; t.x = a; t.y = b;
    return *(uint32_t*)&t;
}

#define SW_ADDR(row, c) (((row) << 8) + ((((c) ^ ((row) & 7))) << 4))

#define LDMX4(r0, r1, r2, r3, ad)                                            \
    asm volatile("ldmatrix.sync.aligned.m8n8.x4.shared.b16 {%0,%1,%2,%3}, [%4];" \
                 : "=r"(r0), "=r"(r1), "=r"(r2), "=r"(r3) : "r"(ad))

#define MMA16816(d, a, b)                                                    \
    asm volatile("mma.sync.aligned.m16n8k16.row.col.f32.bf16.bf16.f32 "      \
                 "{%0,%1,%2,%3}, {%4,%5,%6,%7}, {%8,%9}, {%0,%1,%2,%3};"     \
                 : "+f"((d)[0]), "+f"((d)[1]), "+f"((d)[2]), "+f"((d)[3])    \
                 : "r"((a)[0]), "r"((a)[1]), "r"((a)[2]), "r"((a)[3]),       \
                   "r"((b)[0]), "r"((b)[1]))

// cp.async 16B with zero-fill when pred==0
#define CP16(dst, src, pred)                                                 \
    asm volatile("{ .reg .u32 sz; .reg .pred p; setp.ne.u32 p, %2, 0;\n\t"   \
                 "selp.u32 sz, 16, 0, p;\n\t"                                \
                 "cp.async.cg.shared.global [%0], [%1], 16, sz; }"           \
                 :: "r"(dst), "l"(src), "r"((uint32_t)(pred)) : "memory")
#define CP16U(dst, src)                                                      \
    asm volatile("cp.async.cg.shared.global [%0], [%1], 16;"                 \
                 :: "r"(dst), "l"(src) : "memory")
#define CP_WAIT_ALL()                                                        \
    do { asm volatile("cp.async.commit_group;" ::: "memory");                \
         asm volatile("cp.async.wait_group 0;" ::: "memory"); } while (0)

// ---------------- fused weight prep ----------------
__global__ void wprep(const float* __restrict__ lin_w, const float* __restrict__ msg_w1,
                      const float* __restrict__ whh,
                      __nv_bfloat16* __restrict__ oh, __nv_bfloat16* __restrict__ ol)
{
    const int idx = blockIdx.x * 256 + threadIdx.x;
    if (idx >= 16384 + NLAYERS * 65536) return;
    float v;
    int outrow, k;
    if (idx < 16384) {
        const int n = idx >> 7; k = idx & 127;
        v = lin_w[(size_t)k * 128 + n];
        outrow = n;
    } else {
        const int idx2 = idx - 16384;
        const int l = idx2 / 65536;
        const int r = idx2 % 65536;
        if (r < 16384) {
            const int n = r >> 7; k = r & 127;
            v = msg_w1[(size_t)l * 144 * 128 + (size_t)k * 128 + n];
            outrow = 128 + l * 512 + n;
        } else {
            const int r2 = r - 16384;
            const int n = r2 >> 7; k = r2 & 127;
            v = whh[(size_t)l * 49152 + r2];
            outrow = 128 + l * 512 + 128 + n;
        }
    }
    const __nv_bfloat16 h = __float2bfloat16_rn(v);
    const size_t o = (size_t)outrow * 128 + k;
    oh[o] = h;
    ol[o] = __float2bfloat16_rn(v - __bfloat162float(h));
}

// Wc^T[n][j] = sum_o W2[j][o]*wih[n][o]; bc[n] = sum_o b2[o]*wih[n][o]
__global__ void wc_kernel(const float* __restrict__ msg_w2, const float* __restrict__ wih,
                          const float* __restrict__ msg_b2,
                          __nv_bfloat16* __restrict__ oh, __nv_bfloat16* __restrict__ ol,
                          float* __restrict__ bc)
{
    const int l = blockIdx.x / 384;
    const int n = blockIdx.x % 384;
    const int j = threadIdx.x;     // 128
    const float* w2 = msg_w2 + (size_t)l * 128 * 128;
    __shared__ float wr[128];
    __shared__ float red[128];
    wr[j] = wih[(size_t)l * 384 * 128 + (size_t)n * 128 + j];
    __syncthreads();
    float acc = 0.f;
    const float* w2r = w2 + (size_t)j * 128;
#pragma unroll 8
    for (int o = 0; o < 128; ++o) acc += w2r[o] * wr[o];
    const __nv_bfloat16 h = __float2bfloat16_rn(acc);
    const size_t outrow = (size_t)(1664 + l * 384 + n);
    oh[outrow * 128 + j] = h;
    ol[outrow * 128 + j] = __float2bfloat16_rn(acc - __bfloat162float(h));
    red[j] = msg_b2[l * 128 + j] * wr[j];
    __syncthreads();
    for (int st = 64; st > 0; st >>= 1) {
        if (j < st) red[j] += red[j + st];
        __syncthreads();
    }
    if (j == 0) bc[l * 384 + n] = red[0];
}

__global__ void deg_kernel(const int* __restrict__ ei, float* __restrict__ deg)
{
    const int e = blockIdx.x * blockDim.x + threadIdx.x;
    if (e < NEDGES) atomicAdd(&deg[__ldg(ei + NEDGES + e)], 1.f);
}

// ---------------- fp32 -> bf16 hi/lo conversion ----------------
__global__ void conv_bf(const float* __restrict__ in,
                        __nv_bfloat16* __restrict__ oh, __nv_bfloat16* __restrict__ ol)
{
    const int idx = blockIdx.x * 256 + threadIdx.x;   // float4 index
    if (idx >= NNODES * 32) return;
    const float4 v = *(const float4*)(in + (size_t)idx * 4);
    const float f[4] = {v.x, v.y, v.z, v.w};
    __nv_bfloat16 h[4], l[4];
#pragma unroll
    for (int j = 0; j < 4; ++j) {
        h[j] = __float2bfloat16_rn(f[j]);
        l[j] = __float2bfloat16_rn(f[j] - __bfloat162float(h[j]));
    }
    *(uint2*)(oh + (size_t)idx * 4) = make_uint2(pkbf(h[0], h[1]), pkbf(h[2], h[3]));
    *(uint2*)(ol + (size_t)idx * 4) = make_uint2(pkbf(l[0], l[1]), pkbf(l[2], l[3]));
}

// ---------------- bf16-split tensor-core GEMM, 128x128 block ---------------
// Warp tile 32x64 (4x2 warps) -> MMA:LDSM ratio 4.0 (was 2.0).
// A pre-split bf16 hi/lo [M][128]. Routing as before:
// If C2==null: C1[r*ldc1+col] = acc + bias1[col] + (rowScale? bias2[col]*rowScale[r])
//              (optional relu; optional bf16 hi/lo mirror to Ob/Ol)
// If C2!=null: col<128 -> C1+bias1 ; col>=128 -> C2[r*384+col-128]+bias2
// smem: Ahi@0 Alo@32768 Bhi@65536 Blo@98304 -> 131072
#define MG_SMEM 131072

__global__ void __launch_bounds__(256, 1)
mma_gemm_bf(const __nv_bfloat16* __restrict__ Ah_g, const __nv_bfloat16* __restrict__ Al_g,
            const __nv_bfloat16* __restrict__ Bh, const __nv_bfloat16* __restrict__ Bl,
            float* __restrict__ C1, int ldc1, float* __restrict__ C2, int M,
            const float* __restrict__ bias1, const float* __restrict__ bias2,
            const float* __restrict__ rowScale, int doRelu,
            __nv_bfloat16* __restrict__ Ob, __nv_bfloat16* __restrict__ Ol)
{
    extern __shared__ char sm[];
    const int tid = threadIdx.x;
    const int m0 = blockIdx.x * 128;
    const int n0 = blockIdx.y * 128;
    const uint32_t smb = smem_u32(sm);

    // ---- A fill: 4096 16B chunks (hi 0..2047, lo 2048..4095) via cp.async ----
#pragma unroll
    for (int p = 0; p < 16; ++p) {
        const int idx = tid + p * 256;
        const int half = idx >> 11;
        const int r = (idx >> 4) & 127, c = idx & 15;
        const __nv_bfloat16* src = half ? Al_g : Ah_g;
        const uint32_t dst = smb + (half ? 32768 : 0) + SW_ADDR(r, c);
        CP16(dst, src + (size_t)(m0 + r) * 128 + c * 8, (m0 + r) < M);
    }
    // ---- B fill: 4096 chunks ----
#pragma unroll
    for (int p = 0; p < 16; ++p) {
        const int idx = tid + p * 256;
        const int half = idx >> 11;
        const int r = (idx >> 4) & 127, c = idx & 15;
        const __nv_bfloat16* src = half ? Bl : Bh;
        const uint32_t dst = smb + (half ? 98304 : 65536) + SW_ADDR(r, c);
        CP16U(dst, src + (size_t)(n0 + r) * 128 + c * 8);
    }
    CP_WAIT_ALL();
    __syncthreads();

    const int wid = tid >> 5, L = tid & 31;
    const int wm = (wid & 3) * 32;     // 4 warps over 128 M
    const int wn = (wid >> 2) * 64;    // 2 warps over 128 N

    float acc[2][8][4];
#pragma unroll
    for (int i = 0; i < 2; ++i)
#pragma unroll
        for (int j = 0; j < 8; ++j)
#pragma unroll
            for (int q = 0; q < 4; ++q) acc[i][j][q] = 0.f;

    const int arow = wm + (L & 15);
    const int acs  = L >> 4;
    const int brow = wn + (L & 7) + ((L & 16) ? 8 : 0);
    const int bcs  = (L >> 3) & 1;

#pragma unroll
    for (int ks = 0; ks < 8; ++ks) {
        const int c0 = ks * 2;
        uint32_t Ah[2][4], Al[2][4];
#pragma unroll
        for (int mf = 0; mf < 2; ++mf) {
            const uint32_t off = SW_ADDR(arow + mf * 16, c0 + acs);
            LDMX4(Ah[mf][0], Ah[mf][1], Ah[mf][2], Ah[mf][3], smb + off);
            LDMX4(Al[mf][0], Al[mf][1], Al[mf][2], Al[mf][3], smb + 32768 + off);
        }
        uint32_t Bhf[8][2], Blf[8][2];
#pragma unroll
        for (int nf = 0; nf < 4; ++nf) {
            const uint32_t off = SW_ADDR(brow + nf * 16, c0 + bcs);
            LDMX4(Bhf[nf * 2][0], Bhf[nf * 2][1], Bhf[nf * 2 + 1][0],
                  Bhf[nf * 2 + 1][1], smb + 65536 + off);
            LDMX4(Blf[nf * 2][0], Blf[nf * 2][1], Blf[nf * 2 + 1][0],
                  Blf[nf * 2 + 1][1], smb + 98304 + off);
        }
#pragma unroll
        for (int mf = 0; mf < 2; ++mf)
#pragma unroll
            for (int j = 0; j < 8; ++j) {
                MMA16816(acc[mf][j], Ah[mf], Bhf[j]);
                MMA16816(acc[mf][j], Ah[mf], Blf[j]);
                MMA16816(acc[mf][j], Al[mf], Bhf[j]);
            }
    }

#pragma unroll
    for (int mf = 0; mf < 2; ++mf) {
        const int rbase = m0 + wm + mf * 16 + (L >> 2);
#pragma unroll
        for (int half = 0; half < 2; ++half) {
            const int r = rbase + half * 8;
            if (r >= M) continue;
            const float rs = rowScale ? __ldg(rowScale + r) : 0.f;
#pragma unroll
            for (int j = 0; j < 8; ++j) {
                const int col = n0 + wn + j * 8 + 2 * (L & 3);
                float o0, o1;
                if (!C2) {
                    o0 = acc[mf][j][half * 2]     + __ldg(bias1 + col);
                    o1 = acc[mf][j][half * 2 + 1] + __ldg(bias1 + col + 1);
                    if (rowScale) {
                        o0 += __ldg(bias2 + col)     * rs;
                        o1 += __ldg(bias2 + col + 1) * rs;
                    }
                    if (doRelu) { o0 = fmaxf(o0, 0.f); o1 = fmaxf(o1, 0.f); }
                    *(float2*)(C1 + (size_t)r * ldc1 + col) = make_float2(o0, o1);
                    if (Ob) {
                        const __nv_bfloat16 h0 = __float2bfloat16_rn(o0);
                        const __nv_bfloat16 h1 = __float2bfloat16_rn(o1);
                        *(uint32_t*)(Ob + (size_t)r * 128 + col) = pkbf(h0, h1);
                        *(uint32_t*)(Ol + (size_t)r * 128 + col) = pkbf(
                            __float2bfloat16_rn(o0 - __bfloat162float(h0)),
                            __float2bfloat16_rn(o1 - __bfloat162float(h1)));
                    }
                } else if (col < 128) {
                    o0 = acc[mf][j][half * 2]     + __ldg(bias1 + col);
                    o1 = acc[mf][j][half * 2 + 1] + __ldg(bias1 + col + 1);
                    *(float2*)(C1 + (size_t)r * ldc1 + col) = make_float2(o0, o1);
                } else {
                    const int c2 = col - 128;
                    o0 = acc[mf][j][half * 2]     + __ldg(bias2 + c2);
                    o1 = acc[mf][j][half * 2 + 1] + __ldg(bias2 + c2 + 1);
                    *(float2*)(C2 + (size_t)r * 384 + c2) = make_float2(o0, o1);
                }
            }
        }
    }
}

// ---------------- edge kernel: tensor-core eproj + scatter (R12) ----------
#define ET_W1H 0
#define ET_W1L 6144
#define ET_AH  12288
#define ET_AL  15360
#define ET_EP  18432
#define ET_SMEM 52224
#define NTILES (NEDGES / 64)

__global__ void __launch_bounds__(256)
edge_mma_kernel(const int* __restrict__ ei, const float* __restrict__ ea,
                const float* __restrict__ t, float* __restrict__ s,
                const float* __restrict__ w1e)
{
    extern __shared__ char sm[];
    const int tid = threadIdx.x;
    const int wid = tid >> 5, L = tid & 31;
    const uint32_t smb = smem_u32(sm);

    for (int i = tid; i < 2048; i += 256) {
        const int n = i >> 4, k = i & 15;
        const float v = __ldg(w1e + k * 128 + n);
        const __nv_bfloat16 hb = __float2bfloat16_rn(v);
        *(__nv_bfloat16*)(sm + ET_W1H + n * 48 + k * 2) = hb;
        *(__nv_bfloat16*)(sm + ET_W1L + n * 48 + k * 2) =
            __float2bfloat16_rn(v - __bfloat162float(hb));
    }
    __syncthreads();

    const int mb = wid & 3;
    const int nbase = (wid >> 2) * 64;
    const uint32_t aoff = (uint32_t)((mb * 16 + (L & 15)) * 48 + (L >> 4) * 16);
    const int eaEdge = tid >> 2;
    const int eaK = (tid & 3) * 4;

    for (int tile = blockIdx.x; tile < NTILES; tile += gridDim.x) {
        const int e0 = tile * 64;
        {
            const float4 v = *(const float4*)(ea + (size_t)e0 * 16 + tid * 4);
            const float f[4] = {v.x, v.y, v.z, v.w};
            __nv_bfloat16 hh[4], ll[4];
#pragma unroll
            for (int j = 0; j < 4; ++j) {
                hh[j] = __float2bfloat16_rn(f[j]);
                ll[j] = __float2bfloat16_rn(f[j] - __bfloat162float(hh[j]));
            }
            const int a = eaEdge * 48 + eaK * 2;
            *(uint32_t*)(sm + ET_AH + a)     = pkbf(hh[0], hh[1]);
            *(uint32_t*)(sm + ET_AH + a + 4) = pkbf(hh[2], hh[3]);
            *(uint32_t*)(sm + ET_AL + a)     = pkbf(ll[0], ll[1]);
            *(uint32_t*)(sm + ET_AL + a + 4) = pkbf(ll[2], ll[3]);
        }
        __syncthreads();

        uint32_t Ah[4], Al[4];
        LDMX4(Ah[0], Ah[1], Ah[2], Ah[3], smb + ET_AH + aoff);
        LDMX4(Al[0], Al[1], Al[2], Al[3], smb + ET_AL + aoff);
        float acc[8][4];
#pragma unroll
        for (int j = 0; j < 8; ++j)
#pragma unroll
            for (int q = 0; q < 4; ++q) acc[j][q] = 0.f;

#pragma unroll
        for (int nf = 0; nf < 4; ++nf) {
            const uint32_t boff = (uint32_t)((nbase + nf * 16 + (L & 7) +
                                  ((L & 16) ? 8 : 0)) * 48 + ((L >> 3) & 1) * 16);
            uint32_t Bh0[2], Bh1[2], Bl0[2], Bl1[2];
            LDMX4(Bh0[0], Bh0[1], Bh1[0], Bh1[1], smb + ET_W1H + boff);
            LDMX4(Bl0[0], Bl0[1], Bl1[0], Bl1[1], smb + ET_W1L + boff);
            MMA16816(acc[nf * 2], Ah, Bh0);
            MMA16816(acc[nf * 2], Ah, Bl0);
            MMA16816(acc[nf * 2], Al, Bh0);
            MMA16816(acc[nf * 2 + 1], Ah, Bh1);
            MMA16816(acc[nf * 2 + 1], Ah, Bl1);
            MMA16816(acc[nf * 2 + 1], Al, Bh1);
        }
#pragma unroll
        for (int j = 0; j < 8; ++j) {
            const int col = nbase + j * 8 + 2 * (L & 3);
#pragma unroll
            for (int half = 0; half < 2; ++half) {
                const int row = mb * 16 + (L >> 2) + half * 8;
                *(float2*)(sm + ET_EP + row * 528 + col * 4) =
                    make_float2(acc[j][half * 2], acc[j][half * 2 + 1]);
            }
        }
        __syncthreads();

#pragma unroll
        for (int i = 0; i < 8; ++i) {
            const int eL = wid * 8 + i;
            const int e = e0 + eL;
            const int src = __ldg(ei + e);
            const int dst = __ldg(ei + NEDGES + e);
            const float4 ep = *(const float4*)(sm + ET_EP + eL * 528 + L * 16);
            const float4 tv = *(const float4*)(t + (size_t)src * 128 + L * 4);
            float4 m;
            m.x = fmaxf(tv.x + ep.x, 0.f);
            m.y = fmaxf(tv.y + ep.y, 0.f);
            m.z = fmaxf(tv.z + ep.z, 0.f);
            m.w = fmaxf(tv.w + ep.w, 0.f);
            float* p = s + (size_t)dst * 128 + L * 4;
            asm volatile("red.global.add.v4.f32 [%0], {%1,%2,%3,%4};"
                         :: "l"(p), "f"(m.x), "f"(m.y), "f"(m.z), "f"(m.w)
                         : "memory");
        }
        __syncthreads();
    }
}

// ---------------- fused GRU + BN + residual (+ bf16 mirror out) ----------
__device__ __forceinline__ float gru1(float ir, float iz, float in_, float hr,
                                      float hz, float hn, float h,
                                      float ga, float be, float mu, float va)
{
    const float r = 1.f / (1.f + expf(-(ir + hr)));
    const float z = 1.f / (1.f + expf(-(iz + hz)));
    const float n = tanhf(in_ + r * hn);
    const float hnew = (1.f - z) * n + z * h;
    const float bn = (hnew - mu) * rsqrtf(va + BN_EPS) * ga + be;
    return h + bn;
}

__global__ void gru_bn_kernel(const float* __restrict__ gi, const float* __restrict__ gh,
                              float* __restrict__ h,
                              __nv_bfloat16* __restrict__ hb, __nv_bfloat16* __restrict__ hl,
                              const float* __restrict__ gamma, const float* __restrict__ beta,
                              const float* __restrict__ mean,  const float* __restrict__ var)
{
    const int idx = blockIdx.x * blockDim.x + threadIdx.x;
    if (idx >= NNODES * 32) return;
    const int m = idx >> 5;
    const int c = idx & 31;
    const size_t gb = (size_t)m * 384 + c * 4;
    const float4 ir = *(const float4*)(gi + gb);
    const float4 iz = *(const float4*)(gi + gb + 128);
    const float4 in_ = *(const float4*)(gi + gb + 256);
    const float4 hr = *(const float4*)(gh + gb);
    const float4 hz = *(const float4*)(gh + gb + 128);
    const float4 hn = *(const float4*)(gh + gb + 256);
    float4 hv = *(float4*)(h + (size_t)m * 128 + c * 4);
    const float4 ga = *(const float4*)(gamma + c * 4);
    const float4 be = *(const float4*)(beta + c * 4);
    const float4 mu = *(const float4*)(mean + c * 4);
    const float4 va = *(const float4*)(var + c * 4);
    hv.x = gru1(ir.x, iz.x, in_.x, hr.x, hz.x, hn.x, hv.x, ga.x, be.x, mu.x, va.x);
    hv.y = gru1(ir.y, iz.y, in_.y, hr.y, hz.y, hn.y, hv.y, ga.y, be.y, mu.y, va.y);
    hv.z = gru1(ir.z, iz.z, in_.z, hr.z, hz.z, hn.z, hv.z, ga.z, be.z, mu.z, va.z);
    hv.w = gru1(ir.w, iz.w, in_.w, hr.w, hz.w, hn.w, hv.w, ga.w, be.w, mu.w, va.w);
    *(float4*)(h + (size_t)m * 128 + c * 4) = hv;
    const float f[4] = {hv.x, hv.y, hv.z, hv.w};
    __nv_bfloat16 hh[4], ll[4];
#pragma unroll
    for (int j = 0; j < 4; ++j) {
        hh[j] = __float2bfloat16_rn(f[j]);
        ll[j] = __float2bfloat16_rn(f[j] - __bfloat162float(hh[j]));
    }
    *(uint2*)(hb + (size_t)m * 128 + c * 4) = make_uint2(pkbf(hh[0], hh[1]), pkbf(hh[2], hh[3]));
    *(uint2*)(hl + (size_t)m * 128 + c * 4) = make_uint2(pkbf(ll[0], ll[1]), pkbf(ll[2], ll[3]));
}

__global__ void offsets_kernel(const int* __restrict__ batch, int* __restrict__ offs)
{
    const int g = blockIdx.x * blockDim.x + threadIdx.x;
    if (g > NGRAPHS) return;
    int lo = 0, hi = NNODES;
    while (lo < hi) {
        const int mid = (lo + hi) >> 1;
        if (batch[mid] < g) lo = mid + 1; else hi = mid;
    }
    offs[g] = lo;
}

__global__ void readout_kernel(const float* __restrict__ h, const int* __restrict__ offs,
                               float* __restrict__ z)
{
    const int g = blockIdx.x;
    const int d = threadIdx.x;
    const int s0 = offs[g], e0 = offs[g + 1];
    float sum = 0.f, mx = -INFINITY;
    for (int r = s0; r < e0; ++r) {
        const float v = h[(size_t)r * 128 + d];
        sum += v;
        mx = fmaxf(mx, v);
    }
    const int cnt = e0 - s0;
    float mean = sum / fmaxf((float)cnt, 1.f);
    if (cnt == 0) { mean = 0.f; mx = 0.f; }
    z[g * 256 + d] = mean;
    z[g * 256 + 128 + d] = mx;
}

__global__ void ro_kernel(const float* __restrict__ z, const float* __restrict__ w,
                          const float* __restrict__ b, float* __restrict__ out)
{
    const int g = blockIdx.x;
    const int n = threadIdx.x;
    __shared__ float zs[256];
    zs[n] = z[g * 256 + n];
    zs[n + 128] = z[g * 256 + 128 + n];
    __syncthreads();
    float acc = b[n];
#pragma unroll 8
    for (int k = 0; k < 256; ++k)
        acc += zs[k] * w[k * 128 + n];
    out[g * 128 + n] = fmaxf(acc, 0.f);
}

// ---------------- host ----------------
extern "C" void kernel_launch(void* const* d_in, const int* in_sizes, int n_in,
                              void* d_out, int out_size)
{
    const float* x     = (const float*)d_in[0];
    const int*   ei    = (const int*)d_in[1];
    const float* ea    = (const float*)d_in[2];
    const int*   batch = (const int*)d_in[3];
    const int base = (n_in >= 21) ? 5 : 4;
    const float* lin_w  = (const float*)d_in[base + 0];
    const float* lin_b  = (const float*)d_in[base + 1];
    const float* msg_w1 = (const float*)d_in[base + 2];
    const float* msg_b1 = (const float*)d_in[base + 3];
    const float* msg_w2 = (const float*)d_in[base + 4];
    const float* msg_b2 = (const float*)d_in[base + 5];
    const float* bn_g   = (const float*)d_in[base + 6];
    const float* bn_b   = (const float*)d_in[base + 7];
    const float* bn_m   = (const float*)d_in[base + 8];
    const float* bn_v   = (const float*)d_in[base + 9];
    const float* wih    = (const float*)d_in[base + 10];
    const float* whh    = (const float*)d_in[base + 11];
    const float* bih    = (const float*)d_in[base + 12];
    const float* bhh    = (const float*)d_in[base + 13];
    const float* ro_w   = (const float*)d_in[base + 14];
    const float* ro_b   = (const float*)d_in[base + 15];
    float* out = (float*)d_out;

    float *h, *t, *s, *gi, *gh, *deg, *z, *bc;
    int* offs;
    __nv_bfloat16 *wh_, *wl_, *xb, *xl, *hb, *hl, *sb, *sl;
    cudaGetSymbolAddress((void**)&h,   g_h);
    cudaGetSymbolAddress((void**)&t,   g_t);
    cudaGetSymbolAddress((void**)&s,   g_s);
    cudaGetSymbolAddress((void**)&gi,  g_gi);
    cudaGetSymbolAddress((void**)&gh,  g_gh);
    cudaGetSymbolAddress((void**)&deg, g_deg);
    cudaGetSymbolAddress((void**)&offs, g_offs);
    cudaGetSymbolAddress((void**)&z,   g_z);
    cudaGetSymbolAddress((void**)&bc,  g_bc);
    cudaGetSymbolAddress((void**)&wh_, g_wh);
    cudaGetSymbolAddress((void**)&wl_, g_wl);
    cudaGetSymbolAddress((void**)&xb,  g_xb);
    cudaGetSymbolAddress((void**)&xl,  g_xl);
    cudaGetSymbolAddress((void**)&hb,  g_hb);
    cudaGetSymbolAddress((void**)&hl,  g_hl);
    cudaGetSymbolAddress((void**)&sb,  g_sb);
    cudaGetSymbolAddress((void**)&sl,  g_sl);

    cudaFuncSetAttribute(mma_gemm_bf,
                         cudaFuncAttributeMaxDynamicSharedMemorySize, MG_SMEM);
    cudaFuncSetAttribute(edge_mma_kernel,
                         cudaFuncAttributeMaxDynamicSharedMemorySize, ET_SMEM);

    // weight prep
    wprep<<<(16384 + NLAYERS * 65536 + 255) / 256, 256>>>(lin_w, msg_w1, whh, wh_, wl_);
    wc_kernel<<<NLAYERS * 384, 128>>>(msg_w2, wih, msg_b2, wh_, wl_, bc);

    cudaMemsetAsync(deg, 0, NNODES * sizeof(float), 0);
    deg_kernel<<<(NEDGES + 255) / 256, 256>>>(ei, deg);

    // x -> bf16 hi/lo
    conv_bf<<<(NNODES * 32 + 255) / 256, 256>>>(x, xb, xl);

    const int gx = (NNODES + 127) / 128;

    // h = relu(x @ lin_w + lin_b), also emit hb/hl
    {
        dim3 grid(gx, 1);
        mma_gemm_bf<<<grid, 256, MG_SMEM>>>(xb, xl, wh_, wl_, h, 128, nullptr,
                                            NNODES, lin_b, nullptr, nullptr, 1,
                                            hb, hl);
    }

    for (int l = 0; l < NLAYERS; ++l) {
        const float* W1e = msg_w1 + (size_t)l * 144 * 128 + 128 * 128;
        const int wbase = 128 + l * 512;
        const int cbase = 1664 + l * 384;

        // [t | gh] = h @ [w1h; whh]^T
        {
            dim3 grid(gx, 4);
            mma_gemm_bf<<<grid, 256, MG_SMEM>>>(
                hb, hl, wh_ + (size_t)wbase * 128, wl_ + (size_t)wbase * 128,
                t, 128, gh, NNODES, msg_b1 + l * 128, bhh + l * 384, nullptr, 0,
                nullptr, nullptr);
        }
        cudaMemsetAsync(s, 0, (size_t)NNODES * HID * sizeof(float), 0);
        edge_mma_kernel<<<1536, 256, ET_SMEM>>>(ei, ea, t, s, W1e);
        // s -> bf16 hi/lo
        conv_bf<<<(NNODES * 32 + 255) / 256, 256>>>(s, sb, sl);
        // gi = s @ Wc + bih + deg*bc
        {
            dim3 grid(gx, 3);
            mma_gemm_bf<<<grid, 256, MG_SMEM>>>(
                sb, sl, wh_ + (size_t)cbase * 128, wl_ + (size_t)cbase * 128,
                gi, 384, nullptr, NNODES, bih + l * 384, bc + l * 384, deg, 0,
                nullptr, nullptr);
        }
        gru_bn_kernel<<<(NNODES * 32 + 255) / 256, 256>>>(
            gi, gh, h, hb, hl, bn_g + l * 128, bn_b + l * 128,
            bn_m + l * 128, bn_v + l * 128);
    }

    offsets_kernel<<<2, 256>>>(batch, offs);
    readout_kernel<<<NGRAPHS, 128>>>(h, offs, z);
    ro_kernel<<<NGRAPHS, 128>>>(z, ro_w, ro_b, out);
}

// round 15
// speedup vs baseline: 1.1055x; 1.1055x over previous
#include <cuda_runtime.h>
#include <cuda_bf16.h>
#include <math.h>
#include <stdint.h>

#define NNODES 50000
#define NEDGES 800000
#define HID    128
#define NLAYERS 3
#define NGRAPHS 256
#define BN_EPS 1e-5f

// ---------------- scratch ----------------
__device__ float g_h[NNODES * HID];
__device__ float g_t[NNODES * HID];
__device__ float g_s[NNODES * HID];
__device__ float g_gi[NNODES * 3 * HID];
__device__ float g_gh[NNODES * 3 * HID];
__device__ float g_deg[NNODES];
__device__ int   g_offs[NGRAPHS + 1];
__device__ float g_z[NGRAPHS * 2 * HID];
__device__ float g_bc[NLAYERS * 384];
// bf16 hi/lo weights [n][k=128]:
// rows 0..127: lin ; layer l: 128+l*512 = [w1h(128); whh(384)] ; wc: 1664+l*384
#define WROWS 2816
__device__ __nv_bfloat16 g_wh[WROWS * 128];
__device__ __nv_bfloat16 g_wl[WROWS * 128];

__device__ __forceinline__ uint32_t smem_u32(const void* p) {
    uint32_t a;
    asm("{ .reg .u64 t; cvta.to.shared.u64 t, %1; cvt.u32.u64 %0, t; }"
        : "=r"(a) : "l"(p));
    return a;
}
__device__ __forceinline__ uint32_t pkbf(__nv_bfloat16 a, __nv_bfloat16 b) {
    __nv_bfloat162 t; t.x = a; t.y = b;
    return *(uint32_t*)&t;
}

#define SW_ADDR(row, c) (((row) << 8) + ((((c) ^ ((row) & 7))) << 4))

#define LDMX4(r0, r1, r2, r3, ad)                                            \
    asm volatile("ldmatrix.sync.aligned.m8n8.x4.shared.b16 {%0,%1,%2,%3}, [%4];" \
                 : "=r"(r0), "=r"(r1), "=r"(r2), "=r"(r3) : "r"(ad))

#define MMA16816(d, a, b)                                                    \
    asm volatile("mma.sync.aligned.m16n8k16.row.col.f32.bf16.bf16.f32 "      \
                 "{%0,%1,%2,%3}, {%4,%5,%6,%7}, {%8,%9}, {%0,%1,%2,%3};"     \
                 : "+f"((d)[0]), "+f"((d)[1]), "+f"((d)[2]), "+f"((d)[3])    \
                 : "r"((a)[0]), "r"((a)[1]), "r"((a)[2]), "r"((a)[3]),       \
                   "r"((b)[0]), "r"((b)[1]))

// ---------------- fused weight prep ----------------
__global__ void wprep(const float* __restrict__ lin_w, const float* __restrict__ msg_w1,
                      const float* __restrict__ whh,
                      __nv_bfloat16* __restrict__ oh, __nv_bfloat16* __restrict__ ol)
{
    const int idx = blockIdx.x * 256 + threadIdx.x;
    if (idx >= 16384 + NLAYERS * 65536) return;
    float v;
    int outrow, k;
    if (idx < 16384) {
        const int n = idx >> 7; k = idx & 127;
        v = lin_w[(size_t)k * 128 + n];
        outrow = n;
    } else {
        const int idx2 = idx - 16384;
        const int l = idx2 / 65536;
        const int r = idx2 % 65536;
        if (r < 16384) {
            const int n = r >> 7; k = r & 127;
            v = msg_w1[(size_t)l * 144 * 128 + (size_t)k * 128 + n];
            outrow = 128 + l * 512 + n;
        } else {
            const int r2 = r - 16384;
            const int n = r2 >> 7; k = r2 & 127;
            v = whh[(size_t)l * 49152 + r2];
            outrow = 128 + l * 512 + 128 + n;
        }
    }
    const __nv_bfloat16 h = __float2bfloat16_rn(v);
    const size_t o = (size_t)outrow * 128 + k;
    oh[o] = h;
    ol[o] = __float2bfloat16_rn(v - __bfloat162float(h));
}

// Wc^T[n][j] = sum_o W2[j][o]*wih[n][o]; bc[n] = sum_o b2[o]*wih[n][o]
__global__ void wc_kernel(const float* __restrict__ msg_w2, const float* __restrict__ wih,
                          const float* __restrict__ msg_b2,
                          __nv_bfloat16* __restrict__ oh, __nv_bfloat16* __restrict__ ol,
                          float* __restrict__ bc)
{
    const int l = blockIdx.x / 384;
    const int n = blockIdx.x % 384;
    const int j = threadIdx.x;     // 128
    const float* w2 = msg_w2 + (size_t)l * 128 * 128;
    __shared__ float wr[128];
    __shared__ float red[128];
    wr[j] = wih[(size_t)l * 384 * 128 + (size_t)n * 128 + j];
    __syncthreads();
    float acc = 0.f;
    const float* w2r = w2 + (size_t)j * 128;
#pragma unroll 8
    for (int o = 0; o < 128; ++o) acc += w2r[o] * wr[o];
    const __nv_bfloat16 h = __float2bfloat16_rn(acc);
    const size_t outrow = (size_t)(1664 + l * 384 + n);
    oh[outrow * 128 + j] = h;
    ol[outrow * 128 + j] = __float2bfloat16_rn(acc - __bfloat162float(h));
    red[j] = msg_b2[l * 128 + j] * wr[j];
    __syncthreads();
    for (int st = 64; st > 0; st >>= 1) {
        if (j < st) red[j] += red[j + st];
        __syncthreads();
    }
    if (j == 0) bc[l * 384 + n] = red[0];
}

__global__ void deg_kernel(const int* __restrict__ ei, float* __restrict__ deg)
{
    const int e = blockIdx.x * blockDim.x + threadIdx.x;
    if (e < NEDGES) atomicAdd(&deg[__ldg(ei + NEDGES + e)], 1.f);
}

// ---------------- bf16-split tensor-core GEMM (R12 structure) --------------
#define MG_SMEM 98304

__global__ void __launch_bounds__(256, 2)
mma_gemm(const float* __restrict__ A, const __nv_bfloat16* __restrict__ Bh,
         const __nv_bfloat16* __restrict__ Bl, float* __restrict__ C1, int ldc1,
         float* __restrict__ C2, int M, const float* __restrict__ bias1,
         const float* __restrict__ bias2, const float* __restrict__ rowScale,
         int doRelu)
{
    extern __shared__ char sm[];
    const int tid = threadIdx.x;
    const int m0 = blockIdx.x * 64;
    const int n0 = blockIdx.y * 128;

#pragma unroll
    for (int p = 0; p < 4; ++p) {
        const int idx = tid + p * 256;
        const int m = idx >> 4, c = idx & 15;
        const int gm = m0 + m;
        float4 v0 = make_float4(0.f, 0.f, 0.f, 0.f), v1 = v0;
        if (gm < M) {
            v0 = *(const float4*)(A + (size_t)gm * 128 + c * 8);
            v1 = *(const float4*)(A + (size_t)gm * 128 + c * 8 + 4);
        }
        const float f[8] = {v0.x, v0.y, v0.z, v0.w, v1.x, v1.y, v1.z, v1.w};
        __nv_bfloat16 h[8], l[8];
#pragma unroll
        for (int j = 0; j < 8; ++j) {
            h[j] = __float2bfloat16_rn(f[j]);
            l[j] = __float2bfloat16_rn(f[j] - __bfloat162float(h[j]));
        }
        uint4 hv, lv;
        hv.x = pkbf(h[0], h[1]); hv.y = pkbf(h[2], h[3]);
        hv.z = pkbf(h[4], h[5]); hv.w = pkbf(h[6], h[7]);
        lv.x = pkbf(l[0], l[1]); lv.y = pkbf(l[2], l[3]);
        lv.z = pkbf(l[4], l[5]); lv.w = pkbf(l[6], l[7]);
        const int a = SW_ADDR(m, c);
        *(uint4*)(sm + a)         = hv;
        *(uint4*)(sm + 16384 + a) = lv;
    }
#pragma unroll
    for (int p = 0; p < 16; ++p) {
        const int idx = tid + p * 256;
        const int half = idx >> 11;
        const int r = (idx >> 4) & 127, c = idx & 15;
        const __nv_bfloat16* src = half ? Bl : Bh;
        const uint4 v = *(const uint4*)(src + (size_t)(n0 + r) * 128 + c * 8);
        *(uint4*)(sm + (half ? 65536 : 32768) + SW_ADDR(r, c)) = v;
    }
    __syncthreads();

    const int wid = tid >> 5, L = tid & 31;
    const int wm = (wid & 1) * 32;
    const int wn = (wid >> 1) * 32;
    const uint32_t smb = smem_u32(sm);

    float acc[2][4][4];
#pragma unroll
    for (int i = 0; i < 2; ++i)
#pragma unroll
        for (int j = 0; j < 4; ++j)
#pragma unroll
            for (int q = 0; q < 4; ++q) acc[i][j][q] = 0.f;

    const int arow = wm + (L & 15);
    const int acs  = L >> 4;
    const int brow = wn + (L & 7) + ((L & 16) ? 8 : 0);
    const int bcs  = (L >> 3) & 1;

#pragma unroll
    for (int ks = 0; ks < 8; ++ks) {
        const int c0 = ks * 2;
        uint32_t Ah[2][4], Al[2][4];
#pragma unroll
        for (int mf = 0; mf < 2; ++mf) {
            const uint32_t off = SW_ADDR(arow + mf * 16, c0 + acs);
            LDMX4(Ah[mf][0], Ah[mf][1], Ah[mf][2], Ah[mf][3], smb + off);
            LDMX4(Al[mf][0], Al[mf][1], Al[mf][2], Al[mf][3], smb + 16384 + off);
        }
        uint32_t Bhf[4][2], Blf[4][2];
#pragma unroll
        for (int nf = 0; nf < 2; ++nf) {
            const uint32_t off = SW_ADDR(brow + nf * 16, c0 + bcs);
            LDMX4(Bhf[nf * 2][0], Bhf[nf * 2][1], Bhf[nf * 2 + 1][0],
                  Bhf[nf * 2 + 1][1], smb + 32768 + off);
            LDMX4(Blf[nf * 2][0], Blf[nf * 2][1], Blf[nf * 2 + 1][0],
                  Blf[nf * 2 + 1][1], smb + 65536 + off);
        }
#pragma unroll
        for (int mf = 0; mf < 2; ++mf)
#pragma unroll
            for (int j = 0; j < 4; ++j) {
                MMA16816(acc[mf][j], Ah[mf], Bhf[j]);
                MMA16816(acc[mf][j], Ah[mf], Blf[j]);
                MMA16816(acc[mf][j], Al[mf], Bhf[j]);
            }
    }

#pragma unroll
    for (int mf = 0; mf < 2; ++mf) {
        const int rbase = m0 + wm + mf * 16 + (L >> 2);
#pragma unroll
        for (int half = 0; half < 2; ++half) {
            const int r = rbase + half * 8;
            if (r >= M) continue;
            const float rs = rowScale ? __ldg(rowScale + r) : 0.f;
#pragma unroll
            for (int j = 0; j < 4; ++j) {
                const int col = n0 + wn + j * 8 + 2 * (L & 3);
                float o0, o1;
                if (!C2) {
                    o0 = acc[mf][j][half * 2]     + __ldg(bias1 + col);
                    o1 = acc[mf][j][half * 2 + 1] + __ldg(bias1 + col + 1);
                    if (rowScale) {
                        o0 += __ldg(bias2 + col)     * rs;
                        o1 += __ldg(bias2 + col + 1) * rs;
                    }
                    if (doRelu) { o0 = fmaxf(o0, 0.f); o1 = fmaxf(o1, 0.f); }
                    *(float2*)(C1 + (size_t)r * ldc1 + col) = make_float2(o0, o1);
                } else if (col < 128) {
                    o0 = acc[mf][j][half * 2]     + __ldg(bias1 + col);
                    o1 = acc[mf][j][half * 2 + 1] + __ldg(bias1 + col + 1);
                    *(float2*)(C1 + (size_t)r * ldc1 + col) = make_float2(o0, o1);
                } else {
                    const int c2 = col - 128;
                    o0 = acc[mf][j][half * 2]     + __ldg(bias2 + c2);
                    o1 = acc[mf][j][half * 2 + 1] + __ldg(bias2 + c2 + 1);
                    *(float2*)(C2 + (size_t)r * 384 + c2) = make_float2(o0, o1);
                }
            }
        }
    }
}

// ---------------- edge kernel: tensor-core eproj + scatter (R12) ----------
#define ET_W1H 0
#define ET_W1L 6144
#define ET_AH  12288
#define ET_AL  15360
#define ET_EP  18432
#define ET_SMEM 52224
#define NTILES (NEDGES / 64)

__global__ void __launch_bounds__(256)
edge_mma_kernel(const int* __restrict__ ei, const float* __restrict__ ea,
                const float* __restrict__ t, float* __restrict__ s,
                const float* __restrict__ w1e)
{
    extern __shared__ char sm[];
    const int tid = threadIdx.x;
    const int wid = tid >> 5, L = tid & 31;
    const uint32_t smb = smem_u32(sm);

    for (int i = tid; i < 2048; i += 256) {
        const int n = i >> 4, k = i & 15;
        const float v = __ldg(w1e + k * 128 + n);
        const __nv_bfloat16 hb = __float2bfloat16_rn(v);
        *(__nv_bfloat16*)(sm + ET_W1H + n * 48 + k * 2) = hb;
        *(__nv_bfloat16*)(sm + ET_W1L + n * 48 + k * 2) =
            __float2bfloat16_rn(v - __bfloat162float(hb));
    }
    __syncthreads();

    const int mb = wid & 3;
    const int nbase = (wid >> 2) * 64;
    const uint32_t aoff = (uint32_t)((mb * 16 + (L & 15)) * 48 + (L >> 4) * 16);
    const int eaEdge = tid >> 2;
    const int eaK = (tid & 3) * 4;

    for (int tile = blockIdx.x; tile < NTILES; tile += gridDim.x) {
        const int e0 = tile * 64;
        {
            const float4 v = *(const float4*)(ea + (size_t)e0 * 16 + tid * 4);
            const float f[4] = {v.x, v.y, v.z, v.w};
            __nv_bfloat16 hh[4], ll[4];
#pragma unroll
            for (int j = 0; j < 4; ++j) {
                hh[j] = __float2bfloat16_rn(f[j]);
                ll[j] = __float2bfloat16_rn(f[j] - __bfloat162float(hh[j]));
            }
            const int a = eaEdge * 48 + eaK * 2;
            *(uint32_t*)(sm + ET_AH + a)     = pkbf(hh[0], hh[1]);
            *(uint32_t*)(sm + ET_AH + a + 4) = pkbf(hh[2], hh[3]);
            *(uint32_t*)(sm + ET_AL + a)     = pkbf(ll[0], ll[1]);
            *(uint32_t*)(sm + ET_AL + a + 4) = pkbf(ll[2], ll[3]);
        }
        __syncthreads();

        uint32_t Ah[4], Al[4];
        LDMX4(Ah[0], Ah[1], Ah[2], Ah[3], smb + ET_AH + aoff);
        LDMX4(Al[0], Al[1], Al[2], Al[3], smb + ET_AL + aoff);
        float acc[8][4];
#pragma unroll
        for (int j = 0; j < 8; ++j)
#pragma unroll
            for (int q = 0; q < 4; ++q) acc[j][q] = 0.f;

#pragma unroll
        for (int nf = 0; nf < 4; ++nf) {
            const uint32_t boff = (uint32_t)((nbase + nf * 16 + (L & 7) +
                                  ((L & 16) ? 8 : 0)) * 48 + ((L >> 3) & 1) * 16);
            uint32_t Bh0[2], Bh1[2], Bl0[2], Bl1[2];
            LDMX4(Bh0[0], Bh0[1], Bh1[0], Bh1[1], smb + ET_W1H + boff);
            LDMX4(Bl0[0], Bl0[1], Bl1[0], Bl1[1], smb + ET_W1L + boff);
            MMA16816(acc[nf * 2], Ah, Bh0);
            MMA16816(acc[nf * 2], Ah, Bl0);
            MMA16816(acc[nf * 2], Al, Bh0);
            MMA16816(acc[nf * 2 + 1], Ah, Bh1);
            MMA16816(acc[nf * 2 + 1], Ah, Bl1);
            MMA16816(acc[nf * 2 + 1], Al, Bh1);
        }
#pragma unroll
        for (int j = 0; j < 8; ++j) {
            const int col = nbase + j * 8 + 2 * (L & 3);
#pragma unroll
            for (int half = 0; half < 2; ++half) {
                const int row = mb * 16 + (L >> 2) + half * 8;
                *(float2*)(sm + ET_EP + row * 528 + col * 4) =
                    make_float2(acc[j][half * 2], acc[j][half * 2 + 1]);
            }
        }
        __syncthreads();

#pragma unroll
        for (int i = 0; i < 8; ++i) {
            const int eL = wid * 8 + i;
            const int e = e0 + eL;
            const int src = __ldg(ei + e);
            const int dst = __ldg(ei + NEDGES + e);
            const float4 ep = *(const float4*)(sm + ET_EP + eL * 528 + L * 16);
            const float4 tv = *(const float4*)(t + (size_t)src * 128 + L * 4);
            float4 m;
            m.x = fmaxf(tv.x + ep.x, 0.f);
            m.y = fmaxf(tv.y + ep.y, 0.f);
            m.z = fmaxf(tv.z + ep.z, 0.f);
            m.w = fmaxf(tv.w + ep.w, 0.f);
            float* p = s + (size_t)dst * 128 + L * 4;
            asm volatile("red.global.add.v4.f32 [%0], {%1,%2,%3,%4};"
                         :: "l"(p), "f"(m.x), "f"(m.y), "f"(m.z), "f"(m.w)
                         : "memory");
        }
        __syncthreads();
    }
}

// ---------------- fused GRU + BN + residual ----------------
__device__ __forceinline__ float gru1(float ir, float iz, float in_, float hr,
                                      float hz, float hn, float h,
                                      float ga, float be, float mu, float va)
{
    const float r = 1.f / (1.f + expf(-(ir + hr)));
    const float z = 1.f / (1.f + expf(-(iz + hz)));
    const float n = tanhf(in_ + r * hn);
    const float hnew = (1.f - z) * n + z * h;
    const float bn = (hnew - mu) * rsqrtf(va + BN_EPS) * ga + be;
    return h + bn;
}

__global__ void gru_bn_kernel(const float* __restrict__ gi, const float* __restrict__ gh,
                              float* __restrict__ h,
                              const float* __restrict__ gamma, const float* __restrict__ beta,
                              const float* __restrict__ mean,  const float* __restrict__ var)
{
    const int idx = blockIdx.x * blockDim.x + threadIdx.x;
    if (idx >= NNODES * 32) return;
    const int m = idx >> 5;
    const int c = idx & 31;
    const size_t gb = (size_t)m * 384 + c * 4;
    const float4 ir = *(const float4*)(gi + gb);
    const float4 iz = *(const float4*)(gi + gb + 128);
    const float4 in_ = *(const float4*)(gi + gb + 256);
    const float4 hr = *(const float4*)(gh + gb);
    const float4 hz = *(const float4*)(gh + gb + 128);
    const float4 hn = *(const float4*)(gh + gb + 256);
    float4 hv = *(float4*)(h + (size_t)m * 128 + c * 4);
    const float4 ga = *(const float4*)(gamma + c * 4);
    const float4 be = *(const float4*)(beta + c * 4);
    const float4 mu = *(const float4*)(mean + c * 4);
    const float4 va = *(const float4*)(var + c * 4);
    hv.x = gru1(ir.x, iz.x, in_.x, hr.x, hz.x, hn.x, hv.x, ga.x, be.x, mu.x, va.x);
    hv.y = gru1(ir.y, iz.y, in_.y, hr.y, hz.y, hn.y, hv.y, ga.y, be.y, mu.y, va.y);
    hv.z = gru1(ir.z, iz.z, in_.z, hr.z, hz.z, hn.z, hv.z, ga.z, be.z, mu.z, va.z);
    hv.w = gru1(ir.w, iz.w, in_.w, hr.w, hz.w, hn.w, hv.w, ga.w, be.w, mu.w, va.w);
    *(float4*)(h + (size_t)m * 128 + c * 4) = hv;
}

__global__ void offsets_kernel(const int* __restrict__ batch, int* __restrict__ offs)
{
    const int g = blockIdx.x * blockDim.x + threadIdx.x;
    if (g > NGRAPHS) return;
    int lo = 0, hi = NNODES;
    while (lo < hi) {
        const int mid = (lo + hi) >> 1;
        if (batch[mid] < g) lo = mid + 1; else hi = mid;
    }
    offs[g] = lo;
}

__global__ void readout_kernel(const float* __restrict__ h, const int* __restrict__ offs,
                               float* __restrict__ z)
{
    const int g = blockIdx.x;
    const int d = threadIdx.x;
    const int s0 = offs[g], e0 = offs[g + 1];
    float sum = 0.f, mx = -INFINITY;
    for (int r = s0; r < e0; ++r) {
        const float v = h[(size_t)r * 128 + d];
        sum += v;
        mx = fmaxf(mx, v);
    }
    const int cnt = e0 - s0;
    float mean = sum / fmaxf((float)cnt, 1.f);
    if (cnt == 0) { mean = 0.f; mx = 0.f; }
    z[g * 256 + d] = mean;
    z[g * 256 + 128 + d] = mx;
}

__global__ void ro_kernel(const float* __restrict__ z, const float* __restrict__ w,
                          const float* __restrict__ b, float* __restrict__ out)
{
    const int g = blockIdx.x;
    const int n = threadIdx.x;
    __shared__ float zs[256];
    zs[n] = z[g * 256 + n];
    zs[n + 128] = z[g * 256 + 128 + n];
    __syncthreads();
    float acc = b[n];
#pragma unroll 8
    for (int k = 0; k < 256; ++k)
        acc += zs[k] * w[k * 128 + n];
    out[g * 128 + n] = fmaxf(acc, 0.f);
}

// ---------------- host ----------------
extern "C" void kernel_launch(void* const* d_in, const int* in_sizes, int n_in,
                              void* d_out, int out_size)
{
    const float* x     = (const float*)d_in[0];
    const int*   ei    = (const int*)d_in[1];
    const float* ea    = (const float*)d_in[2];
    const int*   batch = (const int*)d_in[3];
    const int base = (n_in >= 21) ? 5 : 4;
    const float* lin_w  = (const float*)d_in[base + 0];
    const float* lin_b  = (const float*)d_in[base + 1];
    const float* msg_w1 = (const float*)d_in[base + 2];
    const float* msg_b1 = (const float*)d_in[base + 3];
    const float* msg_w2 = (const float*)d_in[base + 4];
    const float* msg_b2 = (const float*)d_in[base + 5];
    const float* bn_g   = (const float*)d_in[base + 6];
    const float* bn_b   = (const float*)d_in[base + 7];
    const float* bn_m   = (const float*)d_in[base + 8];
    const float* bn_v   = (const float*)d_in[base + 9];
    const float* wih    = (const float*)d_in[base + 10];
    const float* whh    = (const float*)d_in[base + 11];
    const float* bih    = (const float*)d_in[base + 12];
    const float* bhh    = (const float*)d_in[base + 13];
    const float* ro_w   = (const float*)d_in[base + 14];
    const float* ro_b   = (const float*)d_in[base + 15];
    float* out = (float*)d_out;

    float *h, *t, *s, *gi, *gh, *deg, *z, *bc;
    int* offs;
    __nv_bfloat16 *wh_, *wl_;
    cudaGetSymbolAddress((void**)&h,   g_h);
    cudaGetSymbolAddress((void**)&t,   g_t);
    cudaGetSymbolAddress((void**)&s,   g_s);
    cudaGetSymbolAddress((void**)&gi,  g_gi);
    cudaGetSymbolAddress((void**)&gh,  g_gh);
    cudaGetSymbolAddress((void**)&deg, g_deg);
    cudaGetSymbolAddress((void**)&offs, g_offs);
    cudaGetSymbolAddress((void**)&z,   g_z);
    cudaGetSymbolAddress((void**)&bc,  g_bc);
    cudaGetSymbolAddress((void**)&wh_, g_wh);
    cudaGetSymbolAddress((void**)&wl_, g_wl);

    cudaFuncSetAttribute(mma_gemm,
                         cudaFuncAttributeMaxDynamicSharedMemorySize, MG_SMEM);
    cudaFuncSetAttribute(edge_mma_kernel,
                         cudaFuncAttributeMaxDynamicSharedMemorySize, ET_SMEM);

    // Side stream + fork/join events. Created once on the first (uncaptured)
    // call; reused on the capture call so no CUDA API besides launches/events
    // happens inside capture. Captured work is identical on every call.
    static cudaStream_t s1 = nullptr;
    static cudaEvent_t evA = nullptr, evB = nullptr;
    if (!s1) {
        cudaStreamCreateWithFlags(&s1, cudaStreamNonBlocking);
        cudaEventCreateWithFlags(&evA, cudaEventDisableTiming);
        cudaEventCreateWithFlags(&evB, cudaEventDisableTiming);
    }

    // weight prep
    wprep<<<(16384 + NLAYERS * 65536 + 255) / 256, 256>>>(lin_w, msg_w1, whh, wh_, wl_);
    wc_kernel<<<NLAYERS * 384, 128>>>(msg_w2, wih, msg_b2, wh_, wl_, bc);

    cudaMemsetAsync(deg, 0, NNODES * sizeof(float), 0);
    deg_kernel<<<(NEDGES + 255) / 256, 256>>>(ei, deg);

    const int gx = (NNODES + 63) / 64;

    // h = relu(x @ lin_w + lin_b)
    {
        dim3 grid(gx, 1);
        mma_gemm<<<grid, 256, MG_SMEM>>>(x, wh_, wl_, h, 128, nullptr, NNODES,
                                         lin_b, nullptr, nullptr, 1);
    }

    for (int l = 0; l < NLAYERS; ++l) {
        const float* W1e = msg_w1 + (size_t)l * 144 * 128 + 128 * 128;
        const int wbase = 128 + l * 512;      // w1h rows
        const int ghbase = wbase + 128;       // whh rows
        const int cbase = 1664 + l * 384;     // wc rows

        // fork: stream1 computes gh = h @ whh^T + bhh while stream0 does
        // t-GEMM -> s-memset -> edge scatter.
        cudaEventRecord(evA, 0);
        cudaStreamWaitEvent(s1, evA, 0);
        {
            dim3 grid(gx, 3);
            mma_gemm<<<grid, 256, MG_SMEM, s1>>>(
                h, wh_ + (size_t)ghbase * 128, wl_ + (size_t)ghbase * 128,
                gh, 384, nullptr, NNODES, bhh + l * 384, nullptr, nullptr, 0);
        }
        cudaEventRecord(evB, s1);

        // stream0: t = h @ w1h + b1
        {
            dim3 grid(gx, 1);
            mma_gemm<<<grid, 256, MG_SMEM>>>(
                h, wh_ + (size_t)wbase * 128, wl_ + (size_t)wbase * 128,
                t, 128, nullptr, NNODES, msg_b1 + l * 128, nullptr, nullptr, 0);
        }
        cudaMemsetAsync(s, 0, (size_t)NNODES * HID * sizeof(float), 0);
        edge_mma_kernel<<<1536, 256, ET_SMEM>>>(ei, ea, t, s, W1e);

        // join, then gi = s @ Wc + bih + deg*bc
        cudaStreamWaitEvent(0, evB, 0);
        {
            dim3 grid(gx, 3);
            mma_gemm<<<grid, 256, MG_SMEM>>>(
                s, wh_ + (size_t)cbase * 128, wl_ + (size_t)cbase * 128,
                gi, 384, nullptr, NNODES, bih + l * 384, bc + l * 384, deg, 0);
        }
        gru_bn_kernel<<<(NNODES * 32 + 255) / 256, 256>>>(
            gi, gh, h, bn_g + l * 128, bn_b + l * 128, bn_m + l * 128, bn_v + l * 128);
    }

    offsets_kernel<<<2, 256>>>(batch, offs);
    readout_kernel<<<NGRAPHS, 128>>>(h, offs, z);
    ro_kernel<<<NGRAPHS, 128>>>(z, ro_w, ro_b, out);
}

// round 16
// speedup vs baseline: 1.1185x; 1.0117x over previous
#include <cuda_runtime.h>
#include <cuda_bf16.h>
#include <math.h>
#include <stdint.h>

#define NNODES 50000
#define NEDGES 800000
#define HID    128
#define NLAYERS 3
#define NGRAPHS 256
#define BN_EPS 1e-5f

// ---------------- scratch ----------------
__device__ float g_h[NNODES * HID];
__device__ float g_t[NNODES * HID];
__device__ float g_s[NNODES * HID];
__device__ float g_gi[NNODES * 3 * HID];
__device__ float g_gh[NNODES * 3 * HID];
__device__ float g_deg[NNODES];
__device__ int   g_offs[NGRAPHS + 1];
__device__ float g_z[NGRAPHS * 2 * HID];
__device__ float g_bc[NLAYERS * 384];
// bf16 hi/lo weights [n][k=128]:
// rows 0..127: lin ; layer l: 128+l*512 = [w1h(128); whh(384)] ; wc: 1664+l*384
#define WROWS 2816
__device__ __nv_bfloat16 g_wh[WROWS * 128];
__device__ __nv_bfloat16 g_wl[WROWS * 128];

__device__ __forceinline__ uint32_t smem_u32(const void* p) {
    uint32_t a;
    asm("{ .reg .u64 t; cvta.to.shared.u64 t, %1; cvt.u32.u64 %0, t; }"
        : "=r"(a) : "l"(p));
    return a;
}
__device__ __forceinline__ uint32_t pkbf(__nv_bfloat16 a, __nv_bfloat16 b) {
    __nv_bfloat162 t; t.x = a; t.y = b;
    return *(uint32_t*)&t;
}

#define SW_ADDR(row, c) (((row) << 8) + ((((c) ^ ((row) & 7))) << 4))

#define LDMX4(r0, r1, r2, r3, ad)                                            \
    asm volatile("ldmatrix.sync.aligned.m8n8.x4.shared.b16 {%0,%1,%2,%3}, [%4];" \
                 : "=r"(r0), "=r"(r1), "=r"(r2), "=r"(r3) : "r"(ad))

#define MMA16816(d, a, b)                                                    \
    asm volatile("mma.sync.aligned.m16n8k16.row.col.f32.bf16.bf16.f32 "      \
                 "{%0,%1,%2,%3}, {%4,%5,%6,%7}, {%8,%9}, {%0,%1,%2,%3};"     \
                 : "+f"((d)[0]), "+f"((d)[1]), "+f"((d)[2]), "+f"((d)[3])    \
                 : "r"((a)[0]), "r"((a)[1]), "r"((a)[2]), "r"((a)[3]),       \
                   "r"((b)[0]), "r"((b)[1]))

// ---------------- fused weight prep ----------------
__global__ void wprep(const float* __restrict__ lin_w, const float* __restrict__ msg_w1,
                      const float* __restrict__ whh,
                      __nv_bfloat16* __restrict__ oh, __nv_bfloat16* __restrict__ ol)
{
    const int idx = blockIdx.x * 256 + threadIdx.x;
    if (idx >= 16384 + NLAYERS * 65536) return;
    float v;
    int outrow, k;
    if (idx < 16384) {
        const int n = idx >> 7; k = idx & 127;
        v = lin_w[(size_t)k * 128 + n];
        outrow = n;
    } else {
        const int idx2 = idx - 16384;
        const int l = idx2 / 65536;
        const int r = idx2 % 65536;
        if (r < 16384) {
            const int n = r >> 7; k = r & 127;
            v = msg_w1[(size_t)l * 144 * 128 + (size_t)k * 128 + n];
            outrow = 128 + l * 512 + n;
        } else {
            const int r2 = r - 16384;
            const int n = r2 >> 7; k = r2 & 127;
            v = whh[(size_t)l * 49152 + r2];
            outrow = 128 + l * 512 + 128 + n;
        }
    }
    const __nv_bfloat16 h = __float2bfloat16_rn(v);
    const size_t o = (size_t)outrow * 128 + k;
    oh[o] = h;
    ol[o] = __float2bfloat16_rn(v - __bfloat162float(h));
}

// Wc^T[n][j] = sum_o W2[j][o]*wih[n][o]; bc[n] = sum_o b2[o]*wih[n][o]
__global__ void wc_kernel(const float* __restrict__ msg_w2, const float* __restrict__ wih,
                          const float* __restrict__ msg_b2,
                          __nv_bfloat16* __restrict__ oh, __nv_bfloat16* __restrict__ ol,
                          float* __restrict__ bc)
{
    const int l = blockIdx.x / 384;
    const int n = blockIdx.x % 384;
    const int j = threadIdx.x;     // 128
    const float* w2 = msg_w2 + (size_t)l * 128 * 128;
    __shared__ float wr[128];
    __shared__ float red[128];
    wr[j] = wih[(size_t)l * 384 * 128 + (size_t)n * 128 + j];
    __syncthreads();
    float acc = 0.f;
    const float* w2r = w2 + (size_t)j * 128;
#pragma unroll 8
    for (int o = 0; o < 128; ++o) acc += w2r[o] * wr[o];
    const __nv_bfloat16 h = __float2bfloat16_rn(acc);
    const size_t outrow = (size_t)(1664 + l * 384 + n);
    oh[outrow * 128 + j] = h;
    ol[outrow * 128 + j] = __float2bfloat16_rn(acc - __bfloat162float(h));
    red[j] = msg_b2[l * 128 + j] * wr[j];
    __syncthreads();
    for (int st = 64; st > 0; st >>= 1) {
        if (j < st) red[j] += red[j + st];
        __syncthreads();
    }
    if (j == 0) bc[l * 384 + n] = red[0];
}

__global__ void deg_kernel(const int* __restrict__ ei, float* __restrict__ deg)
{
    const int e = blockIdx.x * blockDim.x + threadIdx.x;
    if (e < NEDGES) atomicAdd(&deg[__ldg(ei + NEDGES + e)], 1.f);
}

// ---------------- bf16-split tensor-core GEMM (R12 structure) --------------
#define MG_SMEM 98304

__global__ void __launch_bounds__(256, 2)
mma_gemm(const float* __restrict__ A, const __nv_bfloat16* __restrict__ Bh,
         const __nv_bfloat16* __restrict__ Bl, float* __restrict__ C1, int ldc1,
         float* __restrict__ C2, int M, const float* __restrict__ bias1,
         const float* __restrict__ bias2, const float* __restrict__ rowScale,
         int doRelu)
{
    extern __shared__ char sm[];
    const int tid = threadIdx.x;
    const int m0 = blockIdx.x * 64;
    const int n0 = blockIdx.y * 128;

#pragma unroll
    for (int p = 0; p < 4; ++p) {
        const int idx = tid + p * 256;
        const int m = idx >> 4, c = idx & 15;
        const int gm = m0 + m;
        float4 v0 = make_float4(0.f, 0.f, 0.f, 0.f), v1 = v0;
        if (gm < M) {
            v0 = *(const float4*)(A + (size_t)gm * 128 + c * 8);
            v1 = *(const float4*)(A + (size_t)gm * 128 + c * 8 + 4);
        }
        const float f[8] = {v0.x, v0.y, v0.z, v0.w, v1.x, v1.y, v1.z, v1.w};
        __nv_bfloat16 h[8], l[8];
#pragma unroll
        for (int j = 0; j < 8; ++j) {
            h[j] = __float2bfloat16_rn(f[j]);
            l[j] = __float2bfloat16_rn(f[j] - __bfloat162float(h[j]));
        }
        uint4 hv, lv;
        hv.x = pkbf(h[0], h[1]); hv.y = pkbf(h[2], h[3]);
        hv.z = pkbf(h[4], h[5]); hv.w = pkbf(h[6], h[7]);
        lv.x = pkbf(l[0], l[1]); lv.y = pkbf(l[2], l[3]);
        lv.z = pkbf(l[4], l[5]); lv.w = pkbf(l[6], l[7]);
        const int a = SW_ADDR(m, c);
        *(uint4*)(sm + a)         = hv;
        *(uint4*)(sm + 16384 + a) = lv;
    }
#pragma unroll
    for (int p = 0; p < 16; ++p) {
        const int idx = tid + p * 256;
        const int half = idx >> 11;
        const int r = (idx >> 4) & 127, c = idx & 15;
        const __nv_bfloat16* src = half ? Bl : Bh;
        const uint4 v = *(const uint4*)(src + (size_t)(n0 + r) * 128 + c * 8);
        *(uint4*)(sm + (half ? 65536 : 32768) + SW_ADDR(r, c)) = v;
    }
    __syncthreads();

    const int wid = tid >> 5, L = tid & 31;
    const int wm = (wid & 1) * 32;
    const int wn = (wid >> 1) * 32;
    const uint32_t smb = smem_u32(sm);

    float acc[2][4][4];
#pragma unroll
    for (int i = 0; i < 2; ++i)
#pragma unroll
        for (int j = 0; j < 4; ++j)
#pragma unroll
            for (int q = 0; q < 4; ++q) acc[i][j][q] = 0.f;

    const int arow = wm + (L & 15);
    const int acs  = L >> 4;
    const int brow = wn + (L & 7) + ((L & 16) ? 8 : 0);
    const int bcs  = (L >> 3) & 1;

#pragma unroll
    for (int ks = 0; ks < 8; ++ks) {
        const int c0 = ks * 2;
        uint32_t Ah[2][4], Al[2][4];
#pragma unroll
        for (int mf = 0; mf < 2; ++mf) {
            const uint32_t off = SW_ADDR(arow + mf * 16, c0 + acs);
            LDMX4(Ah[mf][0], Ah[mf][1], Ah[mf][2], Ah[mf][3], smb + off);
            LDMX4(Al[mf][0], Al[mf][1], Al[mf][2], Al[mf][3], smb + 16384 + off);
        }
        uint32_t Bhf[4][2], Blf[4][2];
#pragma unroll
        for (int nf = 0; nf < 2; ++nf) {
            const uint32_t off = SW_ADDR(brow + nf * 16, c0 + bcs);
            LDMX4(Bhf[nf * 2][0], Bhf[nf * 2][1], Bhf[nf * 2 + 1][0],
                  Bhf[nf * 2 + 1][1], smb + 32768 + off);
            LDMX4(Blf[nf * 2][0], Blf[nf * 2][1], Blf[nf * 2 + 1][0],
                  Blf[nf * 2 + 1][1], smb + 65536 + off);
        }
#pragma unroll
        for (int mf = 0; mf < 2; ++mf)
#pragma unroll
            for (int j = 0; j < 4; ++j) {
                MMA16816(acc[mf][j], Ah[mf], Bhf[j]);
                MMA16816(acc[mf][j], Ah[mf], Blf[j]);
                MMA16816(acc[mf][j], Al[mf], Bhf[j]);
            }
    }

#pragma unroll
    for (int mf = 0; mf < 2; ++mf) {
        const int rbase = m0 + wm + mf * 16 + (L >> 2);
#pragma unroll
        for (int half = 0; half < 2; ++half) {
            const int r = rbase + half * 8;
            if (r >= M) continue;
            const float rs = rowScale ? __ldg(rowScale + r) : 0.f;
#pragma unroll
            for (int j = 0; j < 4; ++j) {
                const int col = n0 + wn + j * 8 + 2 * (L & 3);
                float o0, o1;
                if (!C2) {
                    o0 = acc[mf][j][half * 2]     + __ldg(bias1 + col);
                    o1 = acc[mf][j][half * 2 + 1] + __ldg(bias1 + col + 1);
                    if (rowScale) {
                        o0 += __ldg(bias2 + col)     * rs;
                        o1 += __ldg(bias2 + col + 1) * rs;
                    }
                    if (doRelu) { o0 = fmaxf(o0, 0.f); o1 = fmaxf(o1, 0.f); }
                    *(float2*)(C1 + (size_t)r * ldc1 + col) = make_float2(o0, o1);
                } else if (col < 128) {
                    o0 = acc[mf][j][half * 2]     + __ldg(bias1 + col);
                    o1 = acc[mf][j][half * 2 + 1] + __ldg(bias1 + col + 1);
                    *(float2*)(C1 + (size_t)r * ldc1 + col) = make_float2(o0, o1);
                } else {
                    const int c2 = col - 128;
                    o0 = acc[mf][j][half * 2]     + __ldg(bias2 + c2);
                    o1 = acc[mf][j][half * 2 + 1] + __ldg(bias2 + c2 + 1);
                    *(float2*)(C2 + (size_t)r * 384 + c2) = make_float2(o0, o1);
                }
            }
        }
    }
}

// ---------------- edge kernel: tensor-core eproj + scatter (R12) ----------
#define ET_W1H 0
#define ET_W1L 6144
#define ET_AH  12288
#define ET_AL  15360
#define ET_EP  18432
#define ET_SMEM 52224
#define NTILES (NEDGES / 64)

__global__ void __launch_bounds__(256)
edge_mma_kernel(const int* __restrict__ ei, const float* __restrict__ ea,
                const float* __restrict__ t, float* __restrict__ s,
                const float* __restrict__ w1e)
{
    extern __shared__ char sm[];
    const int tid = threadIdx.x;
    const int wid = tid >> 5, L = tid & 31;
    const uint32_t smb = smem_u32(sm);

    for (int i = tid; i < 2048; i += 256) {
        const int n = i >> 4, k = i & 15;
        const float v = __ldg(w1e + k * 128 + n);
        const __nv_bfloat16 hb = __float2bfloat16_rn(v);
        *(__nv_bfloat16*)(sm + ET_W1H + n * 48 + k * 2) = hb;
        *(__nv_bfloat16*)(sm + ET_W1L + n * 48 + k * 2) =
            __float2bfloat16_rn(v - __bfloat162float(hb));
    }
    __syncthreads();

    const int mb = wid & 3;
    const int nbase = (wid >> 2) * 64;
    const uint32_t aoff = (uint32_t)((mb * 16 + (L & 15)) * 48 + (L >> 4) * 16);
    const int eaEdge = tid >> 2;
    const int eaK = (tid & 3) * 4;

    for (int tile = blockIdx.x; tile < NTILES; tile += gridDim.x) {
        const int e0 = tile * 64;
        {
            const float4 v = *(const float4*)(ea + (size_t)e0 * 16 + tid * 4);
            const float f[4] = {v.x, v.y, v.z, v.w};
            __nv_bfloat16 hh[4], ll[4];
#pragma unroll
            for (int j = 0; j < 4; ++j) {
                hh[j] = __float2bfloat16_rn(f[j]);
                ll[j] = __float2bfloat16_rn(f[j] - __bfloat162float(hh[j]));
            }
            const int a = eaEdge * 48 + eaK * 2;
            *(uint32_t*)(sm + ET_AH + a)     = pkbf(hh[0], hh[1]);
            *(uint32_t*)(sm + ET_AH + a + 4) = pkbf(hh[2], hh[3]);
            *(uint32_t*)(sm + ET_AL + a)     = pkbf(ll[0], ll[1]);
            *(uint32_t*)(sm + ET_AL + a + 4) = pkbf(ll[2], ll[3]);
        }
        __syncthreads();

        uint32_t Ah[4], Al[4];
        LDMX4(Ah[0], Ah[1], Ah[2], Ah[3], smb + ET_AH + aoff);
        LDMX4(Al[0], Al[1], Al[2], Al[3], smb + ET_AL + aoff);
        float acc[8][4];
#pragma unroll
        for (int j = 0; j < 8; ++j)
#pragma unroll
            for (int q = 0; q < 4; ++q) acc[j][q] = 0.f;

#pragma unroll
        for (int nf = 0; nf < 4; ++nf) {
            const uint32_t boff = (uint32_t)((nbase + nf * 16 + (L & 7) +
                                  ((L & 16) ? 8 : 0)) * 48 + ((L >> 3) & 1) * 16);
            uint32_t Bh0[2], Bh1[2], Bl0[2], Bl1[2];
            LDMX4(Bh0[0], Bh0[1], Bh1[0], Bh1[1], smb + ET_W1H + boff);
            LDMX4(Bl0[0], Bl0[1], Bl1[0], Bl1[1], smb + ET_W1L + boff);
            MMA16816(acc[nf * 2], Ah, Bh0);
            MMA16816(acc[nf * 2], Ah, Bl0);
            MMA16816(acc[nf * 2], Al, Bh0);
            MMA16816(acc[nf * 2 + 1], Ah, Bh1);
            MMA16816(acc[nf * 2 + 1], Ah, Bl1);
            MMA16816(acc[nf * 2 + 1], Al, Bh1);
        }
#pragma unroll
        for (int j = 0; j < 8; ++j) {
            const int col = nbase + j * 8 + 2 * (L & 3);
#pragma unroll
            for (int half = 0; half < 2; ++half) {
                const int row = mb * 16 + (L >> 2) + half * 8;
                *(float2*)(sm + ET_EP + row * 528 + col * 4) =
                    make_float2(acc[j][half * 2], acc[j][half * 2 + 1]);
            }
        }
        __syncthreads();

#pragma unroll
        for (int i = 0; i < 8; ++i) {
            const int eL = wid * 8 + i;
            const int e = e0 + eL;
            const int src = __ldg(ei + e);
            const int dst = __ldg(ei + NEDGES + e);
            const float4 ep = *(const float4*)(sm + ET_EP + eL * 528 + L * 16);
            const float4 tv = *(const float4*)(t + (size_t)src * 128 + L * 4);
            float4 m;
            m.x = fmaxf(tv.x + ep.x, 0.f);
            m.y = fmaxf(tv.y + ep.y, 0.f);
            m.z = fmaxf(tv.z + ep.z, 0.f);
            m.w = fmaxf(tv.w + ep.w, 0.f);
            float* p = s + (size_t)dst * 128 + L * 4;
            asm volatile("red.global.add.v4.f32 [%0], {%1,%2,%3,%4};"
                         :: "l"(p), "f"(m.x), "f"(m.y), "f"(m.z), "f"(m.w)
                         : "memory");
        }
        __syncthreads();
    }
}

// ---------------- fused GRU + BN + residual ----------------
__device__ __forceinline__ float gru1(float ir, float iz, float in_, float hr,
                                      float hz, float hn, float h,
                                      float ga, float be, float mu, float va)
{
    const float r = 1.f / (1.f + expf(-(ir + hr)));
    const float z = 1.f / (1.f + expf(-(iz + hz)));
    const float n = tanhf(in_ + r * hn);
    const float hnew = (1.f - z) * n + z * h;
    const float bn = (hnew - mu) * rsqrtf(va + BN_EPS) * ga + be;
    return h + bn;
}

__global__ void gru_bn_kernel(const float* __restrict__ gi, const float* __restrict__ gh,
                              float* __restrict__ h,
                              const float* __restrict__ gamma, const float* __restrict__ beta,
                              const float* __restrict__ mean,  const float* __restrict__ var)
{
    const int idx = blockIdx.x * blockDim.x + threadIdx.x;
    if (idx >= NNODES * 32) return;
    const int m = idx >> 5;
    const int c = idx & 31;
    const size_t gb = (size_t)m * 384 + c * 4;
    const float4 ir = *(const float4*)(gi + gb);
    const float4 iz = *(const float4*)(gi + gb + 128);
    const float4 in_ = *(const float4*)(gi + gb + 256);
    const float4 hr = *(const float4*)(gh + gb);
    const float4 hz = *(const float4*)(gh + gb + 128);
    const float4 hn = *(const float4*)(gh + gb + 256);
    float4 hv = *(float4*)(h + (size_t)m * 128 + c * 4);
    const float4 ga = *(const float4*)(gamma + c * 4);
    const float4 be = *(const float4*)(beta + c * 4);
    const float4 mu = *(const float4*)(mean + c * 4);
    const float4 va = *(const float4*)(var + c * 4);
    hv.x = gru1(ir.x, iz.x, in_.x, hr.x, hz.x, hn.x, hv.x, ga.x, be.x, mu.x, va.x);
    hv.y = gru1(ir.y, iz.y, in_.y, hr.y, hz.y, hn.y, hv.y, ga.y, be.y, mu.y, va.y);
    hv.z = gru1(ir.z, iz.z, in_.z, hr.z, hz.z, hn.z, hv.z, ga.z, be.z, mu.z, va.z);
    hv.w = gru1(ir.w, iz.w, in_.w, hr.w, hz.w, hn.w, hv.w, ga.w, be.w, mu.w, va.w);
    *(float4*)(h + (size_t)m * 128 + c * 4) = hv;
}

__global__ void offsets_kernel(const int* __restrict__ batch, int* __restrict__ offs)
{
    const int g = blockIdx.x * blockDim.x + threadIdx.x;
    if (g > NGRAPHS) return;
    int lo = 0, hi = NNODES;
    while (lo < hi) {
        const int mid = (lo + hi) >> 1;
        if (batch[mid] < g) lo = mid + 1; else hi = mid;
    }
    offs[g] = lo;
}

__global__ void readout_kernel(const float* __restrict__ h, const int* __restrict__ offs,
                               float* __restrict__ z)
{
    const int g = blockIdx.x;
    const int d = threadIdx.x;
    const int s0 = offs[g], e0 = offs[g + 1];
    float sum = 0.f, mx = -INFINITY;
    for (int r = s0; r < e0; ++r) {
        const float v = h[(size_t)r * 128 + d];
        sum += v;
        mx = fmaxf(mx, v);
    }
    const int cnt = e0 - s0;
    float mean = sum / fmaxf((float)cnt, 1.f);
    if (cnt == 0) { mean = 0.f; mx = 0.f; }
    z[g * 256 + d] = mean;
    z[g * 256 + 128 + d] = mx;
}

__global__ void ro_kernel(const float* __restrict__ z, const float* __restrict__ w,
                          const float* __restrict__ b, float* __restrict__ out)
{
    const int g = blockIdx.x;
    const int n = threadIdx.x;
    __shared__ float zs[256];
    zs[n] = z[g * 256 + n];
    zs[n + 128] = z[g * 256 + 128 + n];
    __syncthreads();
    float acc = b[n];
#pragma unroll 8
    for (int k = 0; k < 256; ++k)
        acc += zs[k] * w[k * 128 + n];
    out[g * 128 + n] = fmaxf(acc, 0.f);
}

// ---------------- host ----------------
extern "C" void kernel_launch(void* const* d_in, const int* in_sizes, int n_in,
                              void* d_out, int out_size)
{
    const float* x     = (const float*)d_in[0];
    const int*   ei    = (const int*)d_in[1];
    const float* ea    = (const float*)d_in[2];
    const int*   batch = (const int*)d_in[3];
    const int base = (n_in >= 21) ? 5 : 4;
    const float* lin_w  = (const float*)d_in[base + 0];
    const float* lin_b  = (const float*)d_in[base + 1];
    const float* msg_w1 = (const float*)d_in[base + 2];
    const float* msg_b1 = (const float*)d_in[base + 3];
    const float* msg_w2 = (const float*)d_in[base + 4];
    const float* msg_b2 = (const float*)d_in[base + 5];
    const float* bn_g   = (const float*)d_in[base + 6];
    const float* bn_b   = (const float*)d_in[base + 7];
    const float* bn_m   = (const float*)d_in[base + 8];
    const float* bn_v   = (const float*)d_in[base + 9];
    const float* wih    = (const float*)d_in[base + 10];
    const float* whh    = (const float*)d_in[base + 11];
    const float* bih    = (const float*)d_in[base + 12];
    const float* bhh    = (const float*)d_in[base + 13];
    const float* ro_w   = (const float*)d_in[base + 14];
    const float* ro_b   = (const float*)d_in[base + 15];
    float* out = (float*)d_out;

    float *h, *t, *s, *gi, *gh, *deg, *z, *bc;
    int* offs;
    __nv_bfloat16 *wh_, *wl_;
    cudaGetSymbolAddress((void**)&h,   g_h);
    cudaGetSymbolAddress((void**)&t,   g_t);
    cudaGetSymbolAddress((void**)&s,   g_s);
    cudaGetSymbolAddress((void**)&gi,  g_gi);
    cudaGetSymbolAddress((void**)&gh,  g_gh);
    cudaGetSymbolAddress((void**)&deg, g_deg);
    cudaGetSymbolAddress((void**)&offs, g_offs);
    cudaGetSymbolAddress((void**)&z,   g_z);
    cudaGetSymbolAddress((void**)&bc,  g_bc);
    cudaGetSymbolAddress((void**)&wh_, g_wh);
    cudaGetSymbolAddress((void**)&wl_, g_wl);

    cudaFuncSetAttribute(mma_gemm,
                         cudaFuncAttributeMaxDynamicSharedMemorySize, MG_SMEM);
    cudaFuncSetAttribute(edge_mma_kernel,
                         cudaFuncAttributeMaxDynamicSharedMemorySize, ET_SMEM);

    // Side stream + fork/join events (created once, before capture; reused).
    static cudaStream_t s1 = nullptr;
    static cudaEvent_t evA = nullptr, evB = nullptr, evC = nullptr, evP = nullptr;
    if (!s1) {
        cudaStreamCreateWithFlags(&s1, cudaStreamNonBlocking);
        cudaEventCreateWithFlags(&evA, cudaEventDisableTiming);
        cudaEventCreateWithFlags(&evB, cudaEventDisableTiming);
        cudaEventCreateWithFlags(&evC, cudaEventDisableTiming);
        cudaEventCreateWithFlags(&evP, cudaEventDisableTiming);
    }

    // ---- prep fork: s1 runs offsets + deg + wc (independent of wprep) ----
    cudaEventRecord(evA, 0);
    cudaStreamWaitEvent(s1, evA, 0);
    offsets_kernel<<<2, 256, 0, s1>>>(batch, offs);
    cudaMemsetAsync(deg, 0, NNODES * sizeof(float), s1);
    deg_kernel<<<(NEDGES + 255) / 256, 256, 0, s1>>>(ei, deg);
    wc_kernel<<<NLAYERS * 384, 128, 0, s1>>>(msg_w2, wih, msg_b2, wh_, wl_, bc);
    cudaEventRecord(evP, s1);

    // stream0: weight conversion then lin GEMM
    wprep<<<(16384 + NLAYERS * 65536 + 255) / 256, 256>>>(lin_w, msg_w1, whh, wh_, wl_);

    const int gx = (NNODES + 63) / 64;

    // h = relu(x @ lin_w + lin_b)
    {
        dim3 grid(gx, 1);
        mma_gemm<<<grid, 256, MG_SMEM>>>(x, wh_, wl_, h, 128, nullptr, NNODES,
                                         lin_b, nullptr, nullptr, 1);
    }
    cudaStreamWaitEvent(0, evP, 0);   // join prep branch

    for (int l = 0; l < NLAYERS; ++l) {
        const float* W1e = msg_w1 + (size_t)l * 144 * 128 + 128 * 128;
        const int wbase = 128 + l * 512;      // w1h rows
        const int ghbase = wbase + 128;       // whh rows
        const int cbase = 1664 + l * 384;     // wc rows

        // fork: s1 does s-memset (prev gi-GEMM already read s) then gh-GEMM
        cudaEventRecord(evA, 0);
        cudaStreamWaitEvent(s1, evA, 0);
        cudaMemsetAsync(s, 0, (size_t)NNODES * HID * sizeof(float), s1);
        cudaEventRecord(evC, s1);
        {
            dim3 grid(gx, 3);
            mma_gemm<<<grid, 256, MG_SMEM, s1>>>(
                h, wh_ + (size_t)ghbase * 128, wl_ + (size_t)ghbase * 128,
                gh, 384, nullptr, NNODES, bhh + l * 384, nullptr, nullptr, 0);
        }
        cudaEventRecord(evB, s1);

        // stream0: t = h @ w1h + b1, then edge scatter (after memset done)
        {
            dim3 grid(gx, 1);
            mma_gemm<<<grid, 256, MG_SMEM>>>(
                h, wh_ + (size_t)wbase * 128, wl_ + (size_t)wbase * 128,
                t, 128, nullptr, NNODES, msg_b1 + l * 128, nullptr, nullptr, 0);
        }
        cudaStreamWaitEvent(0, evC, 0);
        edge_mma_kernel<<<1536, 256, ET_SMEM>>>(ei, ea, t, s, W1e);

        // join gh, then gi = s @ Wc + bih + deg*bc
        cudaStreamWaitEvent(0, evB, 0);
        {
            dim3 grid(gx, 3);
            mma_gemm<<<grid, 256, MG_SMEM>>>(
                s, wh_ + (size_t)cbase * 128, wl_ + (size_t)cbase * 128,
                gi, 384, nullptr, NNODES, bih + l * 384, bc + l * 384, deg, 0);
        }
        gru_bn_kernel<<<(NNODES * 32 + 255) / 256, 256>>>(
            gi, gh, h, bn_g + l * 128, bn_b + l * 128, bn_m + l * 128, bn_v + l * 128);
    }

    readout_kernel<<<NGRAPHS, 128>>>(h, offs, z);
    ro_kernel<<<NGRAPHS, 128>>>(z, ro_w, ro_b, out);
}